// round 14
// baseline (speedup 1.0000x reference)
#include <cuda_runtime.h>
#include <cuda_fp16.h>
#include <math.h>
#include <stdint.h>

// Problem constants
#define BB 4
#define SS 2048
#define EE 1024
#define HH 16
#define DD 64
#define MROWS (BB*SS)          // 8192

// ---------------------------------------------------------------------------
// Scratch (device globals -- no allocation allowed)
// ---------------------------------------------------------------------------
__device__ float2 g_cs[SS*32];                         // (cos, sin) packed

__device__ __half g_xh[MROWS*EE];                      // x fp16
__device__ __half g_ch[MROWS*EE];                      // ctx fp16
__device__ __half g_wqh[3072*1024];                    // w_qkv^T fp16
__device__ __half g_wph[1024*1024];                    // w_proj^T fp16

// Q (pre-scaled by log2(e)/sqrt(D)), K, V fp16. [bh][s][d]
__device__ __half g_Qh[BB*HH*SS*DD];
__device__ __half g_Kh[BB*HH*SS*DD];
__device__ __half g_Vh[BB*HH*SS*DD];

// Q scale: 1/sqrt(64) * log2(e)  (softmax runs in exp2 domain)
#define QSCALE 0.1803368801111204f

// ---------------------------------------------------------------------------
// PTX helpers (baseline PTX: ldmatrix + mma.sync + cp.async, sm_80-era)
// ---------------------------------------------------------------------------
__device__ __forceinline__ uint32_t smem_u32(const void* p) {
    uint32_t a;
    asm("{ .reg .u64 t; cvta.to.shared.u64 t, %1; cvt.u32.u64 %0, t; }"
        : "=r"(a) : "l"(p));
    return a;
}

#define LDSM_X4(r0, r1, r2, r3, addr) \
    asm volatile("ldmatrix.sync.aligned.m8n8.x4.shared.b16 {%0,%1,%2,%3}, [%4];" \
        : "=r"(r0), "=r"(r1), "=r"(r2), "=r"(r3) : "r"(addr))

#define LDSM_X4_T(r0, r1, r2, r3, addr) \
    asm volatile("ldmatrix.sync.aligned.m8n8.x4.trans.shared.b16 {%0,%1,%2,%3}, [%4];" \
        : "=r"(r0), "=r"(r1), "=r"(r2), "=r"(r3) : "r"(addr))

#define MMA_F16(c, a, b0, b1) \
    asm volatile("mma.sync.aligned.m16n8k16.row.col.f32.f16.f16.f32 " \
        "{%0,%1,%2,%3}, {%4,%5,%6,%7}, {%8,%9}, {%0,%1,%2,%3};" \
        : "+f"((c)[0]), "+f"((c)[1]), "+f"((c)[2]), "+f"((c)[3]) \
        : "r"((a)[0]), "r"((a)[1]), "r"((a)[2]), "r"((a)[3]), \
          "r"(b0), "r"(b1))

#define CP_ASYNC16(dst, src) \
    asm volatile("cp.async.cg.shared.global [%0], [%1], 16;" \
        :: "r"(dst), "l"(src) : "memory")
#define CP_COMMIT() asm volatile("cp.async.commit_group;" ::: "memory")
#define CP_WAIT1() asm volatile("cp.async.wait_group 1;" ::: "memory")
#define CP_WAIT0() asm volatile("cp.async.wait_group 0;" ::: "memory")

__device__ __forceinline__ float fast_exp2(float x) {
    float r;
    asm("ex2.approx.f32 %0, %1;" : "=f"(r) : "f"(x));
    return r;
}

// ---------------------------------------------------------------------------
// Fused prep: convert x, transpose both weights, build rope table.
// ---------------------------------------------------------------------------
__global__ __launch_bounds__(256)
void prep_kernel(const float* __restrict__ x,
                 const float* __restrict__ wq,
                 const float* __restrict__ wp) {
    const int tid = threadIdx.x;
    int blk = blockIdx.x;

    if (blk < 8192) {
        int i = blk * 256 + tid;
        float4 v = ((const float4*)x)[i];
        __half2 h0 = __floats2half2_rn(v.x, v.y);
        __half2 h1 = __floats2half2_rn(v.z, v.w);
        ((uint2*)g_xh)[i] = make_uint2(*reinterpret_cast<uint32_t*>(&h0),
                                       *reinterpret_cast<uint32_t*>(&h1));
        return;
    }
    blk -= 8192;
    if (blk < 4096) {
        __shared__ float t[32][33];
        int bxi = blk >> 5;
        int by = (blk & 31) * 32;
        int which = bxi >= 96;
        const float* in = which ? wp : wq;
        __half* oh = which ? g_wph : g_wqh;
        int C = which ? 1024 : 3072;
        int bx = (which ? (bxi - 96) : bxi) * 32;
        int tx = tid & 31, ty = tid >> 5;
#pragma unroll
        for (int i = ty; i < 32; i += 8)
            t[i][tx] = in[(size_t)(by + i) * C + bx + tx];
        __syncthreads();
#pragma unroll
        for (int i = ty; i < 32; i += 8)
            oh[(size_t)(bx + i) * 1024 + by + tx] = __float2half(t[tx][i]);
        return;
    }
    blk -= 4096;
    {
        int i = blk * 256 + tid;
        if (i >= SS * 32) return;
        int s = i >> 5;
        int j = i & 31;
        double inv = exp2(-(double)(2 * j) * (13.287712379549449 / 64.0));
        double a = (double)s * inv;
        double kd = rint(a * 0.6366197723675814);
        double r = fma(-kd, 1.5707963267948966, a);
        r = fma(-kd, 6.123233995736766e-17, r);
        int kq = ((int)kd) & 3;
        float rf = (float)r;
        float cr = cosf(rf), sr = sinf(rf);
        float c, sn;
        switch (kq) {
            case 0:  c = cr;  sn = sr;  break;
            case 1:  c = -sr; sn = cr;  break;
            case 2:  c = -cr; sn = -sr; break;
            default: c = sr;  sn = -cr; break;
        }
        g_cs[i] = make_float2(c, sn);
    }
}

// ---------------------------------------------------------------------------
// HMMA GEMM (R12/R13 structure): 128x128 tile, K-chunk 64, 3-stage cp.async,
// one barrier per chunk, issue after compute, 2 CTAs/SM.
// ---------------------------------------------------------------------------
#define OFF_A 0
#define OFF_B 16384
#define STAGE_BYTES 32768
#define GEMM_SMEM_BYTES (3*STAGE_BYTES + 1024)

template <int MODE>
__global__ __launch_bounds__(256, 2)
void gemm_mma(const float* __restrict__ bias, float* __restrict__ Cout) {
    extern __shared__ char smem_raw[];
    const uint32_t sb = smem_u32(smem_raw);
    const uint32_t tiles = (sb + 1023u) & ~1023u;

    const __half* Ah = (MODE == 0) ? g_xh : g_ch;
    const __half* Bh = (MODE == 0) ? g_wqh : g_wph;

    const int tid = threadIdx.x;
    const int lane = tid & 31;
    const int warp = tid >> 5;
    const int wm = warp >> 1;
    const int wn = warp & 1;
    const int bm = blockIdx.y * 128;
    const int bn = blockIdx.x * 128;

    float acc[2][8][4];
#pragma unroll
    for (int mt = 0; mt < 2; mt++)
#pragma unroll
        for (int nt = 0; nt < 8; nt++)
#pragma unroll
            for (int c = 0; c < 4; c++) acc[mt][nt][c] = 0.f;

    const int crow = tid >> 3;
    const int cseg = tid & 7;
    const uint32_t s_sw =
        (uint32_t)((crow * 128 + cseg * 16) ^ ((crow & 7) << 4));
    const size_t gA0 = (size_t)(bm + crow) * 1024 + cseg * 8;
    const size_t gB0 = (size_t)(bn + crow) * 1024 + cseg * 8;

#define GEMM_ISSUE(c_, st_) do {                                           \
    uint32_t base_ = tiles + (st_) * STAGE_BYTES;                          \
    size_t gk_ = (size_t)(c_) * 64;                                        \
    _Pragma("unroll")                                                      \
    for (int p_ = 0; p_ < 4; p_++) {                                       \
        uint32_t sw_ = s_sw + p_ * 4096;                                   \
        size_t ga_ = gA0 + gk_ + (size_t)p_ * 32 * 1024;                   \
        size_t gb_ = gB0 + gk_ + (size_t)p_ * 32 * 1024;                   \
        CP_ASYNC16(base_ + OFF_A + sw_, Ah + ga_);                         \
        CP_ASYNC16(base_ + OFF_B + sw_, Bh + gb_);                         \
    }                                                                      \
    CP_COMMIT();                                                           \
} while (0)

    const int mat = lane >> 3;
    const int rr = lane & 7;
    const int a_row_base = wm * 32 + (mat & 1) * 8 + rr;
    const uint32_t a_k16 = (uint32_t)((mat >> 1) * 16);
    const int b_row_base = wn * 64 + (mat >> 1) * 8 + rr;
    const uint32_t b_k16 = (uint32_t)((mat & 1) * 16);

    uint32_t a_rel[2], a_xor[2], b_rel[4], b_xor[4];
#pragma unroll
    for (int mt = 0; mt < 2; mt++) {
        int row = a_row_base + mt * 16;
        a_rel[mt] = (uint32_t)(row * 128);
        a_xor[mt] = (uint32_t)((row & 7) << 4);
    }
#pragma unroll
    for (int p = 0; p < 4; p++) {
        int row = b_row_base + p * 16;
        b_rel[p] = (uint32_t)(row * 128);
        b_xor[p] = (uint32_t)((row & 7) << 4);
    }

    GEMM_ISSUE(0, 0);
    GEMM_ISSUE(1, 1);

#pragma unroll 1
    for (int c = 0; c < 16; c++) {
        if (c + 1 < 16) { CP_WAIT1(); } else { CP_WAIT0(); }
        __syncthreads();
        const uint32_t stg = tiles + (c % 3) * STAGE_BYTES;

#pragma unroll
        for (int ks = 0; ks < 4; ks++) {
            const uint32_t ksb = (uint32_t)(ks * 32);
            uint32_t ah[2][4], bf[4][4];
#pragma unroll
            for (int mt = 0; mt < 2; mt++) {
                uint32_t ka = a_rel[mt] + ((ksb + a_k16) ^ a_xor[mt]);
                LDSM_X4(ah[mt][0], ah[mt][1], ah[mt][2], ah[mt][3],
                        stg + OFF_A + ka);
            }
#pragma unroll
            for (int p = 0; p < 4; p++) {
                uint32_t kb = b_rel[p] + ((ksb + b_k16) ^ b_xor[p]);
                LDSM_X4(bf[p][0], bf[p][1], bf[p][2], bf[p][3],
                        stg + OFF_B + kb);
            }
#pragma unroll
            for (int mt = 0; mt < 2; mt++)
#pragma unroll
                for (int nt = 0; nt < 8; nt++) {
                    int p = nt >> 1, hf = (nt & 1) * 2;
                    MMA_F16(acc[mt][nt], ah[mt], bf[p][hf], bf[p][hf + 1]);
                }
        }
        if (c + 2 < 16) GEMM_ISSUE(c + 2, (c + 2) % 3);
    }

    // ---- epilogue ----
    const int tg = lane & 3;
    const int g = lane >> 2;
    const int colbase = bn + wn * 64;

#pragma unroll
    for (int nt = 0; nt < 8; nt++) {
        float2 bb = *(const float2*)(bias + colbase + nt * 8 + tg * 2);
#pragma unroll
        for (int mt = 0; mt < 2; mt++) {
            acc[mt][nt][0] += bb.x;
            acc[mt][nt][1] += bb.y;
            acc[mt][nt][2] += bb.x;
            acc[mt][nt][3] += bb.y;
        }
    }

    if (MODE == 0) {
        const int sec = colbase >> 10;             // 0=q 1=k 2=v
        const int h = (colbase & 1023) >> 6;
        if (sec < 2) {
#pragma unroll
            for (int mt = 0; mt < 2; mt++) {
                int m0 = bm + wm * 32 + mt * 16 + g;
#pragma unroll
                for (int nt = 0; nt < 4; nt++)
#pragma unroll
                    for (int cc = 0; cc < 4; cc += 2) {
                        int j0 = nt * 8 + tg * 2;
                        int sp = (m0 + (cc >> 1) * 8) & 2047;
                        float2 cs0 = g_cs[(sp << 5) | j0];
                        float2 cs1 = g_cs[(sp << 5) | (j0 + 1)];
                        float a1, a2;
                        a1 = acc[mt][nt][cc];     a2 = acc[mt][nt + 4][cc];
                        acc[mt][nt][cc]       = a1 * cs0.x - a2 * cs0.y;
                        acc[mt][nt + 4][cc]   = a2 * cs0.x + a1 * cs0.y;
                        a1 = acc[mt][nt][cc+1];   a2 = acc[mt][nt + 4][cc+1];
                        acc[mt][nt][cc+1]     = a1 * cs1.x - a2 * cs1.y;
                        acc[mt][nt + 4][cc+1] = a2 * cs1.x + a1 * cs1.y;
                    }
            }
        }
        if (sec == 0) {
#pragma unroll
            for (int mt = 0; mt < 2; mt++)
#pragma unroll
                for (int nt = 0; nt < 8; nt++)
#pragma unroll
                    for (int cc = 0; cc < 4; cc++) acc[mt][nt][cc] *= QSCALE;
        }
        __half* bufh = (sec == 0) ? g_Qh : (sec == 1) ? g_Kh : g_Vh;
#pragma unroll
        for (int mt = 0; mt < 2; mt++) {
            int m0 = bm + wm * 32 + mt * 16 + g;
#pragma unroll
            for (int rh = 0; rh < 2; rh++) {
                int row = m0 + rh * 8;
                int b = row >> 11, sp = row & 2047;
                size_t base = (((size_t)(b * HH + h)) * SS + sp) * DD;
#pragma unroll
                for (int nt = 0; nt < 8; nt++) {
                    int d = nt * 8 + tg * 2;
                    __half2 hv = __floats2half2_rn(acc[mt][nt][rh * 2],
                                                   acc[mt][nt][rh * 2 + 1]);
                    *(__half2*)(bufh + base + d) = hv;
                }
            }
        }
    } else {
#pragma unroll
        for (int mt = 0; mt < 2; mt++) {
            int m0 = bm + wm * 32 + mt * 16 + g;
#pragma unroll
            for (int rh = 0; rh < 2; rh++) {
                int row = m0 + rh * 8;
#pragma unroll
                for (int nt = 0; nt < 8; nt++) {
                    int col = colbase + nt * 8 + tg * 2;
                    float2 v = make_float2(acc[mt][nt][rh * 2],
                                           acc[mt][nt][rh * 2 + 1]);
                    *(float2*)(Cout + (size_t)row * EE + col) = v;
                }
            }
        }
    }
#undef GEMM_ISSUE
}

// ---------------------------------------------------------------------------
// Tensor-core flash attention, fp16 operands, exp2-domain softmax with
// fp16x2 MUFU exps (halved MUFU pressure; P emerges pre-packed for PV).
// 3-stage cp.async K/V pipeline, one barrier per tile, issue after compute.
// ---------------------------------------------------------------------------
#define FQH 0
#define FKV0 16384
#define FKV_STAGE 16384
#define FLASH_SMEM_BYTES (FKV0 + 3*FKV_STAGE + 1024)

__global__ __launch_bounds__(256, 2)
void flash_mma() {
    extern __shared__ char smem_raw[];
    const uint32_t sb = smem_u32(smem_raw);
    const uint32_t tiles = (sb + 1023u) & ~1023u;
    char* tp = smem_raw + (tiles - sb);

    const int tid = threadIdx.x;
    const int lane = tid & 31;
    const int warp = tid >> 5;
    const int bh = blockIdx.y;
    const int qb = (int)(gridDim.x - 1 - blockIdx.x);   // heavy blocks first
    const int q0 = qb * 128;
    const size_t qkv_base = (size_t)bh * SS * DD;
    const int ktiles = 2 * qb + 2;

#define FLASH_ISSUE(kt_, st_) do {                                         \
    uint32_t kb_ = tiles + FKV0 + (st_) * FKV_STAGE;                       \
    size_t g0_ = qkv_base + (size_t)(kt_) * 64 * 64;                       \
    _Pragma("unroll")                                                      \
    for (int i_ = 0; i_ < 2; i_++) {                                       \
        int line_ = tid + i_ * 256;                                        \
        int row_ = line_ >> 3, seg_ = line_ & 7;                           \
        uint32_t sw_ =                                                     \
            (uint32_t)((row_ * 128 + seg_ * 16) ^ ((row_ & 7) << 4));      \
        size_t ga_ = g0_ + (size_t)row_ * 64 + seg_ * 8;                   \
        CP_ASYNC16(kb_ + sw_, g_Kh + ga_);                                 \
        CP_ASYNC16(kb_ + 8192 + sw_, g_Vh + ga_);                          \
    }                                                                      \
    CP_COMMIT();                                                           \
} while (0)

    FLASH_ISSUE(0, 0);
    if (ktiles > 1) FLASH_ISSUE(1, 1);

    // ---- load Q tile (128 x 64) into smem ----
#pragma unroll
    for (int i = 0; i < 4; i++) {
        int sidx = tid + i * 256;
        int row = sidx >> 3, sg = sidx & 7;
        uint32_t sw = (uint32_t)((row * 128 + sg * 16) ^ ((row & 7) << 4));
        size_t go = qkv_base + (size_t)(q0 + row) * DD + sg * 8;
        *(uint4*)(tp + FQH + sw) = *(const uint4*)(g_Qh + go);
    }
    __syncthreads();

    const int mat = lane >> 3;
    const int rr = lane & 7;
    const int g = lane >> 2;
    const int tg = lane & 3;

    const int q_row = warp * 16 + (mat & 1) * 8 + rr;
    const uint32_t q_roff = (uint32_t)(q_row * 128);
    const uint32_t q_xor = (uint32_t)((q_row & 7) << 4);
    const uint32_t q_d16 = (uint32_t)((mat >> 1) * 16);

    float O[8][4];
#pragma unroll
    for (int nt = 0; nt < 8; nt++)
#pragma unroll
        for (int c = 0; c < 4; c++) O[nt][c] = 0.f;
    float mrow[2] = {-INFINITY, -INFINITY};
    float lrow[2] = {0.f, 0.f};

    const int k_rowb = (mat >> 1) * 8 + rr;
    const uint32_t k_k16 = (uint32_t)((mat & 1) * 16);
    const int v_rowb = (mat & 1) * 8 + rr;
    const uint32_t v_d16 = (uint32_t)((mat >> 1) * 16);

    const int warp_row_min = q0 + warp * 16;
    const int warp_row_max = warp_row_min + 15;

#pragma unroll 1
    for (int kt = 0; kt < ktiles; kt++) {
        const int k0 = kt * 64;
        if (kt + 1 < ktiles) { CP_WAIT1(); } else { CP_WAIT0(); }
        __syncthreads();
        const uint32_t stgK = tiles + FKV0 + (kt % 3) * FKV_STAGE;
        const uint32_t stgV = stgK + 8192;

        // ---- scores S = Q K^T (log2 units; skip fully-masked blocks) ----
        float s[8][4];
#pragma unroll
        for (int nt = 0; nt < 8; nt++)
#pragma unroll
            for (int c = 0; c < 4; c++) s[nt][c] = 0.f;

#pragma unroll
        for (int ks = 0; ks < 4; ks++) {
            uint32_t qcol = (uint32_t)(ks * 32) + q_d16;
            uint32_t aq[4];
            LDSM_X4(aq[0], aq[1], aq[2], aq[3],
                    tiles + FQH + q_roff + (qcol ^ q_xor));
#pragma unroll
            for (int np = 0; np < 4; np++) {
                if (k0 + np * 16 <= warp_row_max) {
                    int row = np * 16 + k_rowb;
                    uint32_t roff = (uint32_t)(row * 128);
                    uint32_t x = (uint32_t)((row & 7) << 4);
                    uint32_t col = (uint32_t)(ks * 32) + k_k16;
                    uint32_t kh[4];
                    LDSM_X4(kh[0], kh[1], kh[2], kh[3],
                            stgK + roff + (col ^ x));
                    MMA_F16(s[2*np],   aq, kh[0], kh[1]);
                    MMA_F16(s[2*np+1], aq, kh[2], kh[3]);
                }
            }
        }

        // ---- causal mask (partial blocks only) ----
        if (k0 + 63 > warp_row_min) {
#pragma unroll
            for (int nt = 0; nt < 8; nt++)
#pragma unroll
                for (int c = 0; c < 4; c++) {
                    int col = k0 + nt * 8 + tg * 2 + (c & 1);
                    int rw = warp_row_min + g + (c >> 1) * 8;
                    if (col > rw) s[nt][c] = -1e30f;
                }
        }

        // ---- online softmax (exp2 domain, fp16x2 exps) ----
        uint32_t ph2[8][2];   // [nt][rh] packed half2 probabilities
#pragma unroll
        for (int rh = 0; rh < 2; rh++) {
            float vm = -INFINITY;
#pragma unroll
            for (int nt = 0; nt < 8; nt++)
                vm = fmaxf(vm, fmaxf(s[nt][rh*2], s[nt][rh*2+1]));
            vm = fmaxf(vm, __shfl_xor_sync(0xffffffffu, vm, 1));
            vm = fmaxf(vm, __shfl_xor_sync(0xffffffffu, vm, 2));
            float mn = fmaxf(mrow[rh], vm);
            float sc = fast_exp2(mrow[rh] - mn);
            mrow[rh] = mn;
            lrow[rh] *= sc;
            float psum = 0.f;
#pragma unroll
            for (int nt = 0; nt < 8; nt++) {
                __half2 dh = __floats2half2_rn(s[nt][rh*2]   - mn,
                                               s[nt][rh*2+1] - mn);
                __half2 pe = h2exp2(dh);
                ph2[nt][rh] = *reinterpret_cast<uint32_t*>(&pe);
                float2 pf = __half22float2(pe);
                psum += pf.x + pf.y;
                O[nt][rh*2]   *= sc;
                O[nt][rh*2+1] *= sc;
            }
            lrow[rh] += psum;
        }

        // ---- O += P V (P already packed; skip fully-masked key blocks) ----
#pragma unroll
        for (int ks = 0; ks < 4; ks++) {
            if (k0 + ks * 16 > warp_row_max) continue;   // P block is zero
            uint32_t ph[4];
            ph[0] = ph2[2*ks][0];
            ph[1] = ph2[2*ks][1];
            ph[2] = ph2[2*ks+1][0];
            ph[3] = ph2[2*ks+1][1];

            int row = ks * 16 + v_rowb;
            uint32_t roff = (uint32_t)(row * 128);
            uint32_t x = (uint32_t)((row & 7) << 4);
#pragma unroll
            for (int dp = 0; dp < 4; dp++) {
                uint32_t col = (uint32_t)(dp * 32) + v_d16;
                uint32_t vh[4];
                LDSM_X4_T(vh[0], vh[1], vh[2], vh[3],
                          stgV + roff + (col ^ x));
                MMA_F16(O[2*dp],   ph, vh[0], vh[1]);
                MMA_F16(O[2*dp+1], ph, vh[2], vh[3]);
            }
        }
        if (kt + 2 < ktiles) FLASH_ISSUE(kt + 2, (kt + 2) % 3);
    }

    // ---- epilogue: 1/l, write ctx fp16 ----
    float inv[2];
#pragma unroll
    for (int rh = 0; rh < 2; rh++) {
        float l = lrow[rh];
        l += __shfl_xor_sync(0xffffffffu, l, 1);
        l += __shfl_xor_sync(0xffffffffu, l, 2);
        inv[rh] = 1.f / l;
    }
    const int b = bh >> 4, h = bh & 15;
#pragma unroll
    for (int rh = 0; rh < 2; rh++) {
        int sp = q0 + warp * 16 + g + rh * 8;
        size_t base = ((size_t)(b * SS + sp)) * EE + h * DD;
#pragma unroll
        for (int nt = 0; nt < 8; nt++) {
            int d = nt * 8 + tg * 2;
            __half2 hv = __floats2half2_rn(O[nt][rh*2] * inv[rh],
                                           O[nt][rh*2+1] * inv[rh]);
            *(__half2*)(g_ch + base + d) = hv;
        }
    }
#undef FLASH_ISSUE
}

// ---------------------------------------------------------------------------
// Launch
// ---------------------------------------------------------------------------
extern "C" void kernel_launch(void* const* d_in, const int* in_sizes, int n_in,
                              void* d_out, int out_size) {
    const float* x      = (const float*)d_in[0];   // [4,2048,1024]
    const float* w_qkv  = (const float*)d_in[1];   // [1024,3072]
    const float* b_qkv  = (const float*)d_in[2];   // [3072]
    const float* w_proj = (const float*)d_in[3];   // [1024,1024]
    const float* b_proj = (const float*)d_in[4];   // [1024]
    float* out = (float*)d_out;                    // [4,2048,1024]

    cudaFuncSetAttribute(gemm_mma<0>, cudaFuncAttributeMaxDynamicSharedMemorySize,
                         GEMM_SMEM_BYTES);
    cudaFuncSetAttribute(gemm_mma<1>, cudaFuncAttributeMaxDynamicSharedMemorySize,
                         GEMM_SMEM_BYTES);
    cudaFuncSetAttribute(flash_mma, cudaFuncAttributeMaxDynamicSharedMemorySize,
                         FLASH_SMEM_BYTES);

    // 1) Fused prep: convert x + transpose weights + rope table (one launch)
    prep_kernel<<<8192 + 4096 + 256, 256>>>(x, w_qkv, w_proj);

    // 2) QKV GEMM (HMMA) -> fp16 Q/K/V with fused bias+RoPE+scale
    gemm_mma<0><<<dim3(24, 64), 256, GEMM_SMEM_BYTES>>>(b_qkv, nullptr);

    // 3) Tensor-core flash attention (fp16, fp16x2 exp2 softmax) -> fp16 ctx
    flash_mma<<<dim3(SS / 128, BB * HH), 256, FLASH_SMEM_BYTES>>>();

    // 4) Output projection (HMMA) -> d_out
    gemm_mma<1><<<dim3(8, 64), 256, GEMM_SMEM_BYTES>>>(b_proj, out);
}

// round 15
// speedup vs baseline: 1.0272x; 1.0272x over previous
#include <cuda_runtime.h>
#include <cuda_fp16.h>
#include <math.h>
#include <stdint.h>

// Problem constants
#define BB 4
#define SS 2048
#define EE 1024
#define HH 16
#define DD 64
#define MROWS (BB*SS)          // 8192

// ---------------------------------------------------------------------------
// Scratch (device globals -- no allocation allowed)
// ---------------------------------------------------------------------------
__device__ float2 g_cs[SS*32];                         // (cos, sin) packed

__device__ __half g_xh[MROWS*EE];                      // x fp16
__device__ __half g_ch[MROWS*EE];                      // ctx fp16
__device__ __half g_wqh[3072*1024];                    // w_qkv^T fp16
__device__ __half g_wph[1024*1024];                    // w_proj^T fp16

// Q (pre-scaled by log2(e)/sqrt(D)), K, V fp16. [bh][s][d]
__device__ __half g_Qh[BB*HH*SS*DD];
__device__ __half g_Kh[BB*HH*SS*DD];
__device__ __half g_Vh[BB*HH*SS*DD];

// Q scale: 1/sqrt(64) * log2(e)  (softmax runs in exp2 domain)
#define QSCALE 0.1803368801111204f

// ---------------------------------------------------------------------------
// PTX helpers (baseline PTX: ldmatrix + mma.sync + cp.async, sm_80-era)
// ---------------------------------------------------------------------------
__device__ __forceinline__ uint32_t smem_u32(const void* p) {
    uint32_t a;
    asm("{ .reg .u64 t; cvta.to.shared.u64 t, %1; cvt.u32.u64 %0, t; }"
        : "=r"(a) : "l"(p));
    return a;
}

#define LDSM_X4(r0, r1, r2, r3, addr) \
    asm volatile("ldmatrix.sync.aligned.m8n8.x4.shared.b16 {%0,%1,%2,%3}, [%4];" \
        : "=r"(r0), "=r"(r1), "=r"(r2), "=r"(r3) : "r"(addr))

#define LDSM_X4_T(r0, r1, r2, r3, addr) \
    asm volatile("ldmatrix.sync.aligned.m8n8.x4.trans.shared.b16 {%0,%1,%2,%3}, [%4];" \
        : "=r"(r0), "=r"(r1), "=r"(r2), "=r"(r3) : "r"(addr))

#define MMA_F16(c, a, b0, b1) \
    asm volatile("mma.sync.aligned.m16n8k16.row.col.f32.f16.f16.f32 " \
        "{%0,%1,%2,%3}, {%4,%5,%6,%7}, {%8,%9}, {%0,%1,%2,%3};" \
        : "+f"((c)[0]), "+f"((c)[1]), "+f"((c)[2]), "+f"((c)[3]) \
        : "r"((a)[0]), "r"((a)[1]), "r"((a)[2]), "r"((a)[3]), \
          "r"(b0), "r"(b1))

#define CP_ASYNC16(dst, src) \
    asm volatile("cp.async.cg.shared.global [%0], [%1], 16;" \
        :: "r"(dst), "l"(src) : "memory")
#define CP_COMMIT() asm volatile("cp.async.commit_group;" ::: "memory")
#define CP_WAIT1() asm volatile("cp.async.wait_group 1;" ::: "memory")
#define CP_WAIT0() asm volatile("cp.async.wait_group 0;" ::: "memory")

__device__ __forceinline__ float fast_exp2(float x) {
    float r;
    asm("ex2.approx.f32 %0, %1;" : "=f"(r) : "f"(x));
    return r;
}

// ---------------------------------------------------------------------------
// Fused prep: convert x, transpose both weights, build rope table.
// ---------------------------------------------------------------------------
__global__ __launch_bounds__(256)
void prep_kernel(const float* __restrict__ x,
                 const float* __restrict__ wq,
                 const float* __restrict__ wp) {
    const int tid = threadIdx.x;
    int blk = blockIdx.x;

    if (blk < 8192) {
        int i = blk * 256 + tid;
        float4 v = ((const float4*)x)[i];
        __half2 h0 = __floats2half2_rn(v.x, v.y);
        __half2 h1 = __floats2half2_rn(v.z, v.w);
        ((uint2*)g_xh)[i] = make_uint2(*reinterpret_cast<uint32_t*>(&h0),
                                       *reinterpret_cast<uint32_t*>(&h1));
        return;
    }
    blk -= 8192;
    if (blk < 4096) {
        __shared__ float t[32][33];
        int bxi = blk >> 5;
        int by = (blk & 31) * 32;
        int which = bxi >= 96;
        const float* in = which ? wp : wq;
        __half* oh = which ? g_wph : g_wqh;
        int C = which ? 1024 : 3072;
        int bx = (which ? (bxi - 96) : bxi) * 32;
        int tx = tid & 31, ty = tid >> 5;
#pragma unroll
        for (int i = ty; i < 32; i += 8)
            t[i][tx] = in[(size_t)(by + i) * C + bx + tx];
        __syncthreads();
#pragma unroll
        for (int i = ty; i < 32; i += 8)
            oh[(size_t)(bx + i) * 1024 + by + tx] = __float2half(t[tx][i]);
        return;
    }
    blk -= 4096;
    {
        int i = blk * 256 + tid;
        if (i >= SS * 32) return;
        int s = i >> 5;
        int j = i & 31;
        double inv = exp2(-(double)(2 * j) * (13.287712379549449 / 64.0));
        double a = (double)s * inv;
        double kd = rint(a * 0.6366197723675814);
        double r = fma(-kd, 1.5707963267948966, a);
        r = fma(-kd, 6.123233995736766e-17, r);
        int kq = ((int)kd) & 3;
        float rf = (float)r;
        float cr = cosf(rf), sr = sinf(rf);
        float c, sn;
        switch (kq) {
            case 0:  c = cr;  sn = sr;  break;
            case 1:  c = -sr; sn = cr;  break;
            case 2:  c = -cr; sn = -sr; break;
            default: c = sr;  sn = -cr; break;
        }
        g_cs[i] = make_float2(c, sn);
    }
}

// ---------------------------------------------------------------------------
// HMMA GEMM (R12/R13 structure): 128x128 tile, K-chunk 64, 3-stage cp.async,
// one barrier per chunk, issue after compute, 2 CTAs/SM.
// ---------------------------------------------------------------------------
#define OFF_A 0
#define OFF_B 16384
#define STAGE_BYTES 32768
#define GEMM_SMEM_BYTES (3*STAGE_BYTES + 1024)

template <int MODE>
__global__ __launch_bounds__(256, 2)
void gemm_mma(const float* __restrict__ bias, float* __restrict__ Cout) {
    extern __shared__ char smem_raw[];
    const uint32_t sb = smem_u32(smem_raw);
    const uint32_t tiles = (sb + 1023u) & ~1023u;

    const __half* Ah = (MODE == 0) ? g_xh : g_ch;
    const __half* Bh = (MODE == 0) ? g_wqh : g_wph;

    const int tid = threadIdx.x;
    const int lane = tid & 31;
    const int warp = tid >> 5;
    const int wm = warp >> 1;
    const int wn = warp & 1;
    const int bm = blockIdx.y * 128;
    const int bn = blockIdx.x * 128;

    float acc[2][8][4];
#pragma unroll
    for (int mt = 0; mt < 2; mt++)
#pragma unroll
        for (int nt = 0; nt < 8; nt++)
#pragma unroll
            for (int c = 0; c < 4; c++) acc[mt][nt][c] = 0.f;

    const int crow = tid >> 3;
    const int cseg = tid & 7;
    const uint32_t s_sw =
        (uint32_t)((crow * 128 + cseg * 16) ^ ((crow & 7) << 4));
    const size_t gA0 = (size_t)(bm + crow) * 1024 + cseg * 8;
    const size_t gB0 = (size_t)(bn + crow) * 1024 + cseg * 8;

#define GEMM_ISSUE(c_, st_) do {                                           \
    uint32_t base_ = tiles + (st_) * STAGE_BYTES;                          \
    size_t gk_ = (size_t)(c_) * 64;                                        \
    _Pragma("unroll")                                                      \
    for (int p_ = 0; p_ < 4; p_++) {                                       \
        uint32_t sw_ = s_sw + p_ * 4096;                                   \
        size_t ga_ = gA0 + gk_ + (size_t)p_ * 32 * 1024;                   \
        size_t gb_ = gB0 + gk_ + (size_t)p_ * 32 * 1024;                   \
        CP_ASYNC16(base_ + OFF_A + sw_, Ah + ga_);                         \
        CP_ASYNC16(base_ + OFF_B + sw_, Bh + gb_);                         \
    }                                                                      \
    CP_COMMIT();                                                           \
} while (0)

    const int mat = lane >> 3;
    const int rr = lane & 7;
    const int a_row_base = wm * 32 + (mat & 1) * 8 + rr;
    const uint32_t a_k16 = (uint32_t)((mat >> 1) * 16);
    const int b_row_base = wn * 64 + (mat >> 1) * 8 + rr;
    const uint32_t b_k16 = (uint32_t)((mat & 1) * 16);

    uint32_t a_rel[2], a_xor[2], b_rel[4], b_xor[4];
#pragma unroll
    for (int mt = 0; mt < 2; mt++) {
        int row = a_row_base + mt * 16;
        a_rel[mt] = (uint32_t)(row * 128);
        a_xor[mt] = (uint32_t)((row & 7) << 4);
    }
#pragma unroll
    for (int p = 0; p < 4; p++) {
        int row = b_row_base + p * 16;
        b_rel[p] = (uint32_t)(row * 128);
        b_xor[p] = (uint32_t)((row & 7) << 4);
    }

    GEMM_ISSUE(0, 0);
    GEMM_ISSUE(1, 1);

#pragma unroll 1
    for (int c = 0; c < 16; c++) {
        if (c + 1 < 16) { CP_WAIT1(); } else { CP_WAIT0(); }
        __syncthreads();
        const uint32_t stg = tiles + (c % 3) * STAGE_BYTES;

#pragma unroll
        for (int ks = 0; ks < 4; ks++) {
            const uint32_t ksb = (uint32_t)(ks * 32);
            uint32_t ah[2][4], bf[4][4];
#pragma unroll
            for (int mt = 0; mt < 2; mt++) {
                uint32_t ka = a_rel[mt] + ((ksb + a_k16) ^ a_xor[mt]);
                LDSM_X4(ah[mt][0], ah[mt][1], ah[mt][2], ah[mt][3],
                        stg + OFF_A + ka);
            }
#pragma unroll
            for (int p = 0; p < 4; p++) {
                uint32_t kb = b_rel[p] + ((ksb + b_k16) ^ b_xor[p]);
                LDSM_X4(bf[p][0], bf[p][1], bf[p][2], bf[p][3],
                        stg + OFF_B + kb);
            }
#pragma unroll
            for (int mt = 0; mt < 2; mt++)
#pragma unroll
                for (int nt = 0; nt < 8; nt++) {
                    int p = nt >> 1, hf = (nt & 1) * 2;
                    MMA_F16(acc[mt][nt], ah[mt], bf[p][hf], bf[p][hf + 1]);
                }
        }
        if (c + 2 < 16) GEMM_ISSUE(c + 2, (c + 2) % 3);
    }

    // ---- epilogue ----
    const int tg = lane & 3;
    const int g = lane >> 2;
    const int colbase = bn + wn * 64;

#pragma unroll
    for (int nt = 0; nt < 8; nt++) {
        float2 bb = *(const float2*)(bias + colbase + nt * 8 + tg * 2);
#pragma unroll
        for (int mt = 0; mt < 2; mt++) {
            acc[mt][nt][0] += bb.x;
            acc[mt][nt][1] += bb.y;
            acc[mt][nt][2] += bb.x;
            acc[mt][nt][3] += bb.y;
        }
    }

    if (MODE == 0) {
        const int sec = colbase >> 10;             // 0=q 1=k 2=v
        const int h = (colbase & 1023) >> 6;
        if (sec < 2) {
#pragma unroll
            for (int mt = 0; mt < 2; mt++) {
                int m0 = bm + wm * 32 + mt * 16 + g;
#pragma unroll
                for (int nt = 0; nt < 4; nt++)
#pragma unroll
                    for (int cc = 0; cc < 4; cc += 2) {
                        int j0 = nt * 8 + tg * 2;
                        int sp = (m0 + (cc >> 1) * 8) & 2047;
                        float2 cs0 = g_cs[(sp << 5) | j0];
                        float2 cs1 = g_cs[(sp << 5) | (j0 + 1)];
                        float a1, a2;
                        a1 = acc[mt][nt][cc];     a2 = acc[mt][nt + 4][cc];
                        acc[mt][nt][cc]       = a1 * cs0.x - a2 * cs0.y;
                        acc[mt][nt + 4][cc]   = a2 * cs0.x + a1 * cs0.y;
                        a1 = acc[mt][nt][cc+1];   a2 = acc[mt][nt + 4][cc+1];
                        acc[mt][nt][cc+1]     = a1 * cs1.x - a2 * cs1.y;
                        acc[mt][nt + 4][cc+1] = a2 * cs1.x + a1 * cs1.y;
                    }
            }
        }
        if (sec == 0) {
#pragma unroll
            for (int mt = 0; mt < 2; mt++)
#pragma unroll
                for (int nt = 0; nt < 8; nt++)
#pragma unroll
                    for (int cc = 0; cc < 4; cc++) acc[mt][nt][cc] *= QSCALE;
        }
        __half* bufh = (sec == 0) ? g_Qh : (sec == 1) ? g_Kh : g_Vh;
#pragma unroll
        for (int mt = 0; mt < 2; mt++) {
            int m0 = bm + wm * 32 + mt * 16 + g;
#pragma unroll
            for (int rh = 0; rh < 2; rh++) {
                int row = m0 + rh * 8;
                int b = row >> 11, sp = row & 2047;
                size_t base = (((size_t)(b * HH + h)) * SS + sp) * DD;
#pragma unroll
                for (int nt = 0; nt < 8; nt++) {
                    int d = nt * 8 + tg * 2;
                    __half2 hv = __floats2half2_rn(acc[mt][nt][rh * 2],
                                                   acc[mt][nt][rh * 2 + 1]);
                    *(__half2*)(bufh + base + d) = hv;
                }
            }
        }
    } else {
#pragma unroll
        for (int mt = 0; mt < 2; mt++) {
            int m0 = bm + wm * 32 + mt * 16 + g;
#pragma unroll
            for (int rh = 0; rh < 2; rh++) {
                int row = m0 + rh * 8;
#pragma unroll
                for (int nt = 0; nt < 8; nt++) {
                    int col = colbase + nt * 8 + tg * 2;
                    float2 v = make_float2(acc[mt][nt][rh * 2],
                                           acc[mt][nt][rh * 2 + 1]);
                    *(float2*)(Cout + (size_t)row * EE + col) = v;
                }
            }
        }
    }
#undef GEMM_ISSUE
}

// ---------------------------------------------------------------------------
// Tensor-core flash attention, fp16 operands, exp2-domain fp32 softmax
// (R13 structure). 3-stage cp.async K/V pipeline, one barrier per tile,
// issue after compute. Warp-uniform skipping of fully-masked key blocks.
// ---------------------------------------------------------------------------
#define FQH 0
#define FKV0 16384
#define FKV_STAGE 16384
#define FLASH_SMEM_BYTES (FKV0 + 3*FKV_STAGE + 1024)

__global__ __launch_bounds__(256, 2)
void flash_mma() {
    extern __shared__ char smem_raw[];
    const uint32_t sb = smem_u32(smem_raw);
    const uint32_t tiles = (sb + 1023u) & ~1023u;
    char* tp = smem_raw + (tiles - sb);

    const int tid = threadIdx.x;
    const int lane = tid & 31;
    const int warp = tid >> 5;
    const int bh = blockIdx.y;
    const int qb = (int)(gridDim.x - 1 - blockIdx.x);   // heavy blocks first
    const int q0 = qb * 128;
    const size_t qkv_base = (size_t)bh * SS * DD;
    const int ktiles = 2 * qb + 2;

#define FLASH_ISSUE(kt_, st_) do {                                         \
    uint32_t kb_ = tiles + FKV0 + (st_) * FKV_STAGE;                       \
    size_t g0_ = qkv_base + (size_t)(kt_) * 64 * 64;                       \
    _Pragma("unroll")                                                      \
    for (int i_ = 0; i_ < 2; i_++) {                                       \
        int line_ = tid + i_ * 256;                                        \
        int row_ = line_ >> 3, seg_ = line_ & 7;                           \
        uint32_t sw_ =                                                     \
            (uint32_t)((row_ * 128 + seg_ * 16) ^ ((row_ & 7) << 4));      \
        size_t ga_ = g0_ + (size_t)row_ * 64 + seg_ * 8;                   \
        CP_ASYNC16(kb_ + sw_, g_Kh + ga_);                                 \
        CP_ASYNC16(kb_ + 8192 + sw_, g_Vh + ga_);                          \
    }                                                                      \
    CP_COMMIT();                                                           \
} while (0)

    FLASH_ISSUE(0, 0);
    if (ktiles > 1) FLASH_ISSUE(1, 1);

    // ---- load Q tile (128 x 64) into smem ----
#pragma unroll
    for (int i = 0; i < 4; i++) {
        int sidx = tid + i * 256;
        int row = sidx >> 3, sg = sidx & 7;
        uint32_t sw = (uint32_t)((row * 128 + sg * 16) ^ ((row & 7) << 4));
        size_t go = qkv_base + (size_t)(q0 + row) * DD + sg * 8;
        *(uint4*)(tp + FQH + sw) = *(const uint4*)(g_Qh + go);
    }
    __syncthreads();

    const int mat = lane >> 3;
    const int rr = lane & 7;
    const int g = lane >> 2;
    const int tg = lane & 3;

    const int q_row = warp * 16 + (mat & 1) * 8 + rr;
    const uint32_t q_roff = (uint32_t)(q_row * 128);
    const uint32_t q_xor = (uint32_t)((q_row & 7) << 4);
    const uint32_t q_d16 = (uint32_t)((mat >> 1) * 16);

    float O[8][4];
#pragma unroll
    for (int nt = 0; nt < 8; nt++)
#pragma unroll
        for (int c = 0; c < 4; c++) O[nt][c] = 0.f;
    float mrow[2] = {-INFINITY, -INFINITY};
    float lrow[2] = {0.f, 0.f};

    const int k_rowb = (mat >> 1) * 8 + rr;
    const uint32_t k_k16 = (uint32_t)((mat & 1) * 16);
    const int v_rowb = (mat & 1) * 8 + rr;
    const uint32_t v_d16 = (uint32_t)((mat >> 1) * 16);

    const int warp_row_min = q0 + warp * 16;
    const int warp_row_max = warp_row_min + 15;

#pragma unroll 1
    for (int kt = 0; kt < ktiles; kt++) {
        const int k0 = kt * 64;
        if (kt + 1 < ktiles) { CP_WAIT1(); } else { CP_WAIT0(); }
        __syncthreads();
        const uint32_t stgK = tiles + FKV0 + (kt % 3) * FKV_STAGE;
        const uint32_t stgV = stgK + 8192;

        // ---- scores S = Q K^T (log2 units; skip fully-masked blocks) ----
        float s[8][4];
#pragma unroll
        for (int nt = 0; nt < 8; nt++)
#pragma unroll
            for (int c = 0; c < 4; c++) s[nt][c] = 0.f;

#pragma unroll
        for (int ks = 0; ks < 4; ks++) {
            uint32_t qcol = (uint32_t)(ks * 32) + q_d16;
            uint32_t aq[4];
            LDSM_X4(aq[0], aq[1], aq[2], aq[3],
                    tiles + FQH + q_roff + (qcol ^ q_xor));
#pragma unroll
            for (int np = 0; np < 4; np++) {
                if (k0 + np * 16 <= warp_row_max) {
                    int row = np * 16 + k_rowb;
                    uint32_t roff = (uint32_t)(row * 128);
                    uint32_t x = (uint32_t)((row & 7) << 4);
                    uint32_t col = (uint32_t)(ks * 32) + k_k16;
                    uint32_t kh[4];
                    LDSM_X4(kh[0], kh[1], kh[2], kh[3],
                            stgK + roff + (col ^ x));
                    MMA_F16(s[2*np],   aq, kh[0], kh[1]);
                    MMA_F16(s[2*np+1], aq, kh[2], kh[3]);
                }
            }
        }

        // ---- causal mask (partial blocks only) ----
        if (k0 + 63 > warp_row_min) {
#pragma unroll
            for (int nt = 0; nt < 8; nt++)
#pragma unroll
                for (int c = 0; c < 4; c++) {
                    int col = k0 + nt * 8 + tg * 2 + (c & 1);
                    int rw = warp_row_min + g + (c >> 1) * 8;
                    if (col > rw) s[nt][c] = -1e30f;
                }
        }

        // ---- online softmax (exp2 domain, f32 exps -- R13 form) ----
#pragma unroll
        for (int rh = 0; rh < 2; rh++) {
            float vm = -INFINITY;
#pragma unroll
            for (int nt = 0; nt < 8; nt++)
                vm = fmaxf(vm, fmaxf(s[nt][rh*2], s[nt][rh*2+1]));
            vm = fmaxf(vm, __shfl_xor_sync(0xffffffffu, vm, 1));
            vm = fmaxf(vm, __shfl_xor_sync(0xffffffffu, vm, 2));
            float mn = fmaxf(mrow[rh], vm);
            float sc = fast_exp2(mrow[rh] - mn);
            mrow[rh] = mn;
            lrow[rh] *= sc;
            float psum = 0.f;
#pragma unroll
            for (int nt = 0; nt < 8; nt++) {
                float p0 = fast_exp2(s[nt][rh*2]   - mn);
                float p1 = fast_exp2(s[nt][rh*2+1] - mn);
                s[nt][rh*2] = p0;
                s[nt][rh*2+1] = p1;
                psum += p0 + p1;
                O[nt][rh*2]   *= sc;
                O[nt][rh*2+1] *= sc;
            }
            lrow[rh] += psum;
        }

        // ---- O += P V (skip fully-masked key blocks) ----
#pragma unroll
        for (int ks = 0; ks < 4; ks++) {
            if (k0 + ks * 16 > warp_row_max) continue;   // P block is zero
            uint32_t ph[4];
            __half2 p01 = __floats2half2_rn(s[2*ks][0], s[2*ks][1]);
            __half2 p23 = __floats2half2_rn(s[2*ks][2], s[2*ks][3]);
            __half2 p45 = __floats2half2_rn(s[2*ks+1][0], s[2*ks+1][1]);
            __half2 p67 = __floats2half2_rn(s[2*ks+1][2], s[2*ks+1][3]);
            ph[0] = *reinterpret_cast<uint32_t*>(&p01);
            ph[1] = *reinterpret_cast<uint32_t*>(&p23);
            ph[2] = *reinterpret_cast<uint32_t*>(&p45);
            ph[3] = *reinterpret_cast<uint32_t*>(&p67);

            int row = ks * 16 + v_rowb;
            uint32_t roff = (uint32_t)(row * 128);
            uint32_t x = (uint32_t)((row & 7) << 4);
#pragma unroll
            for (int dp = 0; dp < 4; dp++) {
                uint32_t col = (uint32_t)(dp * 32) + v_d16;
                uint32_t vh[4];
                LDSM_X4_T(vh[0], vh[1], vh[2], vh[3],
                          stgV + roff + (col ^ x));
                MMA_F16(O[2*dp],   ph, vh[0], vh[1]);
                MMA_F16(O[2*dp+1], ph, vh[2], vh[3]);
            }
        }
        if (kt + 2 < ktiles) FLASH_ISSUE(kt + 2, (kt + 2) % 3);
    }

    // ---- epilogue: 1/l, write ctx fp16 ----
    float inv[2];
#pragma unroll
    for (int rh = 0; rh < 2; rh++) {
        float l = lrow[rh];
        l += __shfl_xor_sync(0xffffffffu, l, 1);
        l += __shfl_xor_sync(0xffffffffu, l, 2);
        inv[rh] = 1.f / l;
    }
    const int b = bh >> 4, h = bh & 15;
#pragma unroll
    for (int rh = 0; rh < 2; rh++) {
        int sp = q0 + warp * 16 + g + rh * 8;
        size_t base = ((size_t)(b * SS + sp)) * EE + h * DD;
#pragma unroll
        for (int nt = 0; nt < 8; nt++) {
            int d = nt * 8 + tg * 2;
            __half2 hv = __floats2half2_rn(O[nt][rh*2] * inv[rh],
                                           O[nt][rh*2+1] * inv[rh]);
            *(__half2*)(g_ch + base + d) = hv;
        }
    }
#undef FLASH_ISSUE
}

// ---------------------------------------------------------------------------
// Launch
// ---------------------------------------------------------------------------
extern "C" void kernel_launch(void* const* d_in, const int* in_sizes, int n_in,
                              void* d_out, int out_size) {
    const float* x      = (const float*)d_in[0];   // [4,2048,1024]
    const float* w_qkv  = (const float*)d_in[1];   // [1024,3072]
    const float* b_qkv  = (const float*)d_in[2];   // [3072]
    const float* w_proj = (const float*)d_in[3];   // [1024,1024]
    const float* b_proj = (const float*)d_in[4];   // [1024]
    float* out = (float*)d_out;                    // [4,2048,1024]

    cudaFuncSetAttribute(gemm_mma<0>, cudaFuncAttributeMaxDynamicSharedMemorySize,
                         GEMM_SMEM_BYTES);
    cudaFuncSetAttribute(gemm_mma<1>, cudaFuncAttributeMaxDynamicSharedMemorySize,
                         GEMM_SMEM_BYTES);
    cudaFuncSetAttribute(flash_mma, cudaFuncAttributeMaxDynamicSharedMemorySize,
                         FLASH_SMEM_BYTES);

    // 1) Fused prep: convert x + transpose weights + rope table (one launch)
    prep_kernel<<<8192 + 4096 + 256, 256>>>(x, w_qkv, w_proj);

    // 2) QKV GEMM (HMMA) -> fp16 Q/K/V with fused bias+RoPE+scale
    gemm_mma<0><<<dim3(24, 64), 256, GEMM_SMEM_BYTES>>>(b_qkv, nullptr);

    // 3) Tensor-core flash attention (fp16, exp2 softmax) -> fp16 ctx
    flash_mma<<<dim3(SS / 128, BB * HH), 256, FLASH_SMEM_BYTES>>>();

    // 4) Output projection (HMMA) -> d_out
    gemm_mma<1><<<dim3(8, 64), 256, GEMM_SMEM_BYTES>>>(b_proj, out);
}